// round 6
// baseline (speedup 1.0000x reference)
#include <cuda_runtime.h>
#include <cstdint>

// ---------------- problem constants ----------------
#define NB         32
#define DD         768
#define EMBD       768
#define NPOS       196
#define ROWS_TOTAL 6272        // = 49 * 128 exactly
#define NC0        512
#define NC1        2048
#define NC2        8192
#define OUTSLICE   4816896     // 32*768*196
#define TAU        0.5f

// score-kernel tiling
#define TM   128
#define TN   256
#define BK   32
#define NCHUNK (DD / BK)       // 24
// smem strides (words) with +8 pad for conflict-free fragment LDS
#define ASTR 136
#define BSTR 264
#define ABYTES (BK * ASTR * 4)           // 17408
#define BBYTES (BK * BSTR * 4)           // 33792
#define BUFB   (ABYTES + BBYTES)         // 51200
#define OFF_NRM  (3 * BUFB)              // 153600
#define OFF_SKEY (OFF_NRM + 1024)        // 154624  (4*128 u64)
#define OFF_SSEC (OFF_SKEY + 4096)       // 158720  (4*128 f32)
#define SMEM_TOTAL (OFF_SSEC + 2048)     // 160768

// ---------------- static scratch ----------------
__device__ float g_X [ROWS_TOTAL * DD];
__device__ float g_D1[ROWS_TOTAL * DD];
__device__ float g_D2[ROWS_TOTAL * DD];
__device__ float g_At [(size_t)DD * ROWS_TOTAL];   // [768][6272] tf32-rounded
__device__ float g_B0t[(size_t)DD * NC0];
__device__ float g_B1t[(size_t)DD * NC1];
__device__ float g_B2t[(size_t)DD * NC2];
__device__ float g_norms[NC0 + NC1 + NC2];
__device__ unsigned long long g_tb[(size_t)ROWS_TOTAL * 32];
__device__ float g_ts[(size_t)ROWS_TOTAL * 32];
__device__ int g_cls0[ROWS_TOTAL];
__device__ int g_cls1[ROWS_TOTAL];
__device__ int g_cls2[ROWS_TOTAL];
__device__ int g_flags[ROWS_TOTAL];
__device__ int g_cnt;

// ---------------- helpers ----------------
__device__ __forceinline__ uint32_t smem_u32(const void* p) {
    uint32_t a;
    asm("{ .reg .u64 t; cvta.to.shared.u64 t, %1; cvt.u32.u64 %0, t; }" : "=r"(a) : "l"(p));
    return a;
}
__device__ __forceinline__ float tf32r(float x) {
    uint32_t r;
    asm("cvt.rna.tf32.f32 %0, %1;" : "=r"(r) : "f"(x));
    return __uint_as_float(r);
}
__device__ __forceinline__ unsigned fkey(float f) {
    unsigned u = __float_as_uint(f);
    return (u & 0x80000000u) ? ~u : (u | 0x80000000u);
}
__device__ __forceinline__ float unkey(unsigned k) {
    unsigned b = (k & 0x80000000u) ? (k & 0x7fffffffu) : ~k;
    return __uint_as_float(b);
}
__device__ __forceinline__ void cp16(uint32_t d, const void* s) {
    asm volatile("cp.async.cg.shared.global [%0], [%1], 16;" :: "r"(d), "l"(s));
}
#define CP_COMMIT() asm volatile("cp.async.commit_group;" ::: "memory")
#define CP_WAIT1()  asm volatile("cp.async.wait_group 1;" ::: "memory")

__device__ __forceinline__ void mma_tf32(float* d, const uint32_t* a, const uint32_t* b) {
    asm volatile(
        "mma.sync.aligned.m16n8k8.row.col.f32.tf32.tf32.f32 "
        "{%0,%1,%2,%3}, {%4,%5,%6,%7}, {%8,%9}, {%0,%1,%2,%3};"
        : "+f"(d[0]), "+f"(d[1]), "+f"(d[2]), "+f"(d[3])
        : "r"(a[0]), "r"(a[1]), "r"(a[2]), "r"(a[3]), "r"(b[0]), "r"(b[1]));
}

// ---------------- patchify ----------------
__global__ void patchify_kernel(const float* __restrict__ data, float* __restrict__ X) {
    int row = blockIdx.x;
    int b = row / NPOS, p = row - b * NPOS;
    int ph = p / 14, pw = p - ph * 14;
    const float* src = data + (size_t)b * 3 * 224 * 224;
    float* dst = X + (size_t)row * DD;
    for (int f = threadIdx.x; f < DD; f += blockDim.x) {
        int c = f >> 8, i = (f >> 4) & 15, j = f & 15;
        dst[f] = src[((size_t)c * 224 + (ph * 16 + i)) * 224 + (pw * 16 + j)];
    }
}

// ---------------- center norms ----------------
__global__ void norms_kernel(const float* __restrict__ C, float* __restrict__ out) {
    int k = blockIdx.x;
    const float* row = C + (size_t)k * DD;
    float s = 0.f;
    for (int i = threadIdx.x; i < DD; i += 256) { float v = row[i]; s += v * v; }
    #pragma unroll
    for (int o = 16; o; o >>= 1) s += __shfl_xor_sync(0xffffffffu, s, o);
    __shared__ float red[8];
    if ((threadIdx.x & 31) == 0) red[threadIdx.x >> 5] = s;
    __syncthreads();
    if (threadIdx.x == 0) {
        float t = 0.f;
        #pragma unroll
        for (int w = 0; w < 8; w++) t += red[w];
        out[k] = t;
    }
}

// ---------------- transpose + tf32-round: src[R][768] -> dst[768][R] ----------------
__global__ void trans_kernel(const float* __restrict__ src, float* __restrict__ dst,
                             int R, int* __restrict__ cnt)
{
    if (cnt && blockIdx.x == 0 && blockIdx.y == 0 && threadIdx.x == 0 && threadIdx.y == 0)
        *cnt = 0;
    __shared__ float t[32][33];
    int bx = blockIdx.x * 32;   // col base (0..767)
    int by = blockIdx.y * 32;   // row base (0..R)
    #pragma unroll
    for (int j = 0; j < 4; j++) {
        int r = by + threadIdx.y + j * 8;
        t[threadIdx.y + j * 8][threadIdx.x] = src[(size_t)r * DD + bx + threadIdx.x];
    }
    __syncthreads();
    #pragma unroll
    for (int j = 0; j < 4; j++) {
        int c = bx + threadIdx.y + j * 8;
        dst[(size_t)c * R + by + threadIdx.x] = tf32r(t[threadIdx.x][threadIdx.y + j * 8]);
    }
}

// ---------------- TF32 mma.sync GEMM (128x256 tile) + fused top-2 ----------------
extern __shared__ char smem_raw[];
__global__ __launch_bounds__(256, 1) void score_mma_kernel(
    const float* __restrict__ At, const float* __restrict__ Bt, int Kn,
    const float* __restrict__ norms,
    unsigned long long* __restrict__ tb, float* __restrict__ ts)
{
    const int tid = threadIdx.x;
    const int w = tid >> 5;
    const int lane = tid & 31;
    const int wm = w & 1;        // 2 M-warps of 64 rows
    const int wn = w >> 1;       // 4 N-warps of 64 cols
    const int m0 = blockIdx.x * TM;
    const int n0 = blockIdx.y * TN;
    const uint32_t sb = smem_u32(smem_raw);
    float* snrm = (float*)(smem_raw + OFF_NRM);
    unsigned long long* skey = (unsigned long long*)(smem_raw + OFF_SKEY);
    float* ssec = (float*)(smem_raw + OFF_SSEC);

    snrm[tid] = norms[n0 + tid];

    float acc[4][8][4];
    #pragma unroll
    for (int mf = 0; mf < 4; mf++)
        #pragma unroll
        for (int nf = 0; nf < 8; nf++)
            #pragma unroll
            for (int j = 0; j < 4; j++) acc[mf][nf][j] = 0.f;

    // cp.async issue of chunk k0 into buffer b
    #define ISSUE(kc_, b_) do { \
        int k0_ = (kc_) * BK; \
        uint32_t abase_ = sb + (uint32_t)(b_) * BUFB; \
        const float* As_ = At + (size_t)k0_ * ROWS_TOTAL + m0; \
        _Pragma("unroll") \
        for (int j_ = 0; j_ < 4; j_++) { \
            int i_ = tid + 256 * j_; \
            int kr_ = i_ >> 5, sg_ = i_ & 31; \
            cp16(abase_ + (uint32_t)(kr_ * ASTR + sg_ * 4) * 4, \
                 As_ + (size_t)kr_ * ROWS_TOTAL + sg_ * 4); \
        } \
        uint32_t bbase_ = abase_ + ABYTES; \
        const float* Bs_ = Bt + (size_t)k0_ * Kn + n0; \
        _Pragma("unroll") \
        for (int j_ = 0; j_ < 8; j_++) { \
            int i_ = tid + 256 * j_; \
            int kr_ = i_ >> 6, sg_ = i_ & 63; \
            cp16(bbase_ + (uint32_t)(kr_ * BSTR + sg_ * 4) * 4, \
                 Bs_ + (size_t)kr_ * Kn + sg_ * 4); \
        } \
    } while (0)

    ISSUE(0, 0); CP_COMMIT();
    ISSUE(1, 1); CP_COMMIT();

    for (int c = 0; c < NCHUNK; c++) {
        CP_WAIT1();
        __syncthreads();
        if (c + 2 < NCHUNK) {
            int bn = (c + 2) % 3;
            ISSUE(c + 2, bn);
        }
        CP_COMMIT();

        const uint32_t* sA = (const uint32_t*)(smem_raw + (c % 3) * BUFB);
        const uint32_t* sBm = (const uint32_t*)(smem_raw + (c % 3) * BUFB + ABYTES);
        #pragma unroll
        for (int k8 = 0; k8 < 4; k8++) {
            const int kA = k8 * 8 + (lane & 3);
            const int mrow = wm * 64 + (lane >> 2);
            const int ncol = wn * 64 + (lane >> 2);
            uint32_t a[4][4], bfr[8][2];
            #pragma unroll
            for (int mf = 0; mf < 4; mf++) {
                a[mf][0] = sA[kA * ASTR + mrow + mf * 16];
                a[mf][1] = sA[kA * ASTR + mrow + mf * 16 + 8];
                a[mf][2] = sA[(kA + 4) * ASTR + mrow + mf * 16];
                a[mf][3] = sA[(kA + 4) * ASTR + mrow + mf * 16 + 8];
            }
            #pragma unroll
            for (int nf = 0; nf < 8; nf++) {
                bfr[nf][0] = sBm[kA * BSTR + ncol + nf * 8];
                bfr[nf][1] = sBm[(kA + 4) * BSTR + ncol + nf * 8];
            }
            #pragma unroll
            for (int mf = 0; mf < 4; mf++)
                #pragma unroll
                for (int nf = 0; nf < 8; nf++)
                    mma_tf32(acc[mf][nf], a[mf], bfr[nf]);
        }
        __syncthreads();
    }
    #undef ISSUE

    // ---------- epilogue: per-row best/second-best ----------
    unsigned long long bkey[8];
    float bsec[8];
    const unsigned long long INITK =
        ((unsigned long long)fkey(3.0e38f) << 32) | 0xffffffffull;
    #pragma unroll
    for (int i = 0; i < 8; i++) { bkey[i] = INITK; bsec[i] = 3.2e38f; }

    #pragma unroll
    for (int mf = 0; mf < 4; mf++) {
        #pragma unroll
        for (int nf = 0; nf < 8; nf++) {
            int cbase = wn * 64 + nf * 8 + 2 * (lane & 3);
            #pragma unroll
            for (int j = 0; j < 4; j++) {
                int c = cbase + (j & 1);
                float s = snrm[c] - 2.f * acc[mf][nf][j];
                int ri = mf * 2 + (j >> 1);
                unsigned long long key =
                    ((unsigned long long)fkey(s) << 32) | (unsigned)(n0 + c);
                if (key < bkey[ri]) {
                    bsec[ri] = unkey((unsigned)(bkey[ri] >> 32));
                    bkey[ri] = key;
                } else if (s < bsec[ri]) {
                    bsec[ri] = s;
                }
            }
        }
    }
    // reduce across the 4 lanes sharing each row (xor 1, 2)
    #pragma unroll
    for (int i = 0; i < 8; i++) {
        #pragma unroll
        for (int m = 1; m <= 2; m <<= 1) {
            unsigned long long ok = __shfl_xor_sync(0xffffffffu, bkey[i], m);
            float os = __shfl_xor_sync(0xffffffffu, bsec[i], m);
            unsigned long long kmin = (ok < bkey[i]) ? ok : bkey[i];
            unsigned long long kmax = (ok < bkey[i]) ? bkey[i] : ok;
            bsec[i] = fminf(fminf(bsec[i], os), unkey((unsigned)(kmax >> 32)));
            bkey[i] = kmin;
        }
    }
    if ((lane & 3) == 0) {
        #pragma unroll
        for (int i = 0; i < 8; i++) {
            int row = wm * 64 + (i >> 1) * 16 + (i & 1) * 8 + (lane >> 2);
            skey[wn * 128 + row] = bkey[i];
            ssec[wn * 128 + row] = bsec[i];
        }
    }
    __syncthreads();
    if (tid < 128) {
        unsigned long long k = skey[tid];
        float s = ssec[tid];
        #pragma unroll
        for (int q = 1; q < 4; q++) {
            unsigned long long ok = skey[q * 128 + tid];
            float os = ssec[q * 128 + tid];
            unsigned long long kmin = (ok < k) ? ok : k;
            unsigned long long kmax = (ok < k) ? k : ok;
            s = fminf(fminf(s, os), unkey((unsigned)(kmax >> 32)));
            k = kmin;
        }
        int row = blockIdx.x * TM + tid;
        tb[(size_t)row * 32 + blockIdx.y] = k;
        ts[(size_t)row * 32 + blockIdx.y] = s;
    }
}

// ---------------- cross-tile top-2 reduce + margin flagging ----------------
__global__ void reduce_kernel(const unsigned long long* __restrict__ tb,
                              const float* __restrict__ ts, int NT,
                              int* __restrict__ cls, int* __restrict__ flags,
                              int* __restrict__ cnt)
{
    int row = blockIdx.x, t = threadIdx.x;
    unsigned long long key = (t < NT) ? tb[(size_t)row * 32 + t] : ~0ull;
    float sec = (t < NT) ? ts[(size_t)row * 32 + t] : 3.4e38f;
    unsigned long long mk = key;
    #pragma unroll
    for (int o = 16; o; o >>= 1) {
        unsigned long long v = __shfl_xor_sync(0xffffffffu, mk, o);
        if (v < mk) mk = v;
    }
    float myb = (t < NT) ? unkey((unsigned)(key >> 32)) : 3.4e38f;
    float cand = (key == mk) ? sec : myb;
    #pragma unroll
    for (int o = 16; o; o >>= 1) {
        float v = __shfl_xor_sync(0xffffffffu, cand, o);
        cand = fminf(cand, v);
    }
    if (t == 0) {
        cls[row] = (int)(mk & 0xffffffffull);
        float bb = unkey((unsigned)(mk >> 32));
        if (cand - bb < TAU) { int i = atomicAdd(cnt, 1); flags[i] = row; }
    }
}

// ---------------- exact fp32 re-argmin for flagged rows ----------------
__global__ __launch_bounds__(256) void fixup_kernel(
    const float* __restrict__ R, const float* __restrict__ C,
    const float* __restrict__ norms, int K,
    const int* __restrict__ flags, const int* __restrict__ cnt,
    int* __restrict__ cls)
{
    __shared__ float xr[DD];
    __shared__ unsigned long long red[256];
    int n = *cnt;
    for (int fi = blockIdx.x; fi < n; fi += gridDim.x) {
        int row = flags[fi];
        for (int i = threadIdx.x; i < DD; i += 256) xr[i] = R[(size_t)row * DD + i];
        __syncthreads();
        unsigned long long bk = ~0ull;
        for (int k = threadIdx.x; k < K; k += 256) {
            const float* cr = C + (size_t)k * DD;
            float d0 = 0.f, d1 = 0.f, d2 = 0.f, d3 = 0.f;
            #pragma unroll 4
            for (int i = 0; i < DD; i += 4) {
                d0 = fmaf(xr[i + 0], cr[i + 0], d0);
                d1 = fmaf(xr[i + 1], cr[i + 1], d1);
                d2 = fmaf(xr[i + 2], cr[i + 2], d2);
                d3 = fmaf(xr[i + 3], cr[i + 3], d3);
            }
            float s = norms[k] - 2.f * ((d0 + d1) + (d2 + d3));
            unsigned long long key = ((unsigned long long)fkey(s) << 32) | (unsigned)k;
            if (key < bk) bk = key;
        }
        red[threadIdx.x] = bk;
        __syncthreads();
        for (int st = 128; st; st >>= 1) {
            if (threadIdx.x < st && red[threadIdx.x + st] < red[threadIdx.x])
                red[threadIdx.x] = red[threadIdx.x + st];
            __syncthreads();
        }
        if (threadIdx.x == 0) cls[row] = (int)(red[0] & 0xffffffffull);
        __syncthreads();
    }
}

// ---------------- residual gather ----------------
__global__ void gather_kernel(const float* __restrict__ prev, const float* __restrict__ C,
                              const int* __restrict__ cls, float* __restrict__ outd)
{
    int row = blockIdx.x;
    int k = cls[row];
    const float4* pr = (const float4*)(prev + (size_t)row * DD);
    const float4* cr = (const float4*)(C + (size_t)k * DD);
    float4* orow = (float4*)(outd + (size_t)row * DD);
    for (int f = threadIdx.x; f < DD / 4; f += blockDim.x) {
        float4 a = pr[f], b = cr[f];
        orow[f] = make_float4(a.x - b.x, a.y - b.y, a.z - b.z, a.w - b.w);
    }
}

// ---------------- outputs ----------------
__global__ void embed_kernel(const float* __restrict__ e0, const float* __restrict__ e1,
                             const float* __restrict__ e2,
                             const int* __restrict__ cls0, const int* __restrict__ cls1,
                             const int* __restrict__ cls2, float* __restrict__ out)
{
    int b = blockIdx.x;
    int ebase = blockIdx.y * 8;
    __shared__ int s0[NPOS], s1[NPOS], s2[NPOS];
    for (int p = threadIdx.x; p < NPOS; p += blockDim.x) {
        int r = b * NPOS + p;
        s0[p] = cls0[r]; s1[p] = cls1[r]; s2[p] = cls2[r];
    }
    __syncthreads();
    for (int idx = threadIdx.x; idx < 8 * NPOS; idx += blockDim.x) {
        int e = ebase + idx / NPOS;
        int p = idx - (idx / NPOS) * NPOS;
        out[((size_t)b * EMBD + e) * NPOS + p] =
            e0[(size_t)s0[p] * EMBD + e] +
            e1[(size_t)s1[p] * EMBD + e] +
            e2[(size_t)s2[p] * EMBD + e];
    }
}

__global__ void img_kernel(const float* __restrict__ X, const float* __restrict__ Df,
                           float* __restrict__ out)
{
    int b = blockIdx.x, c = blockIdx.y, h = blockIdx.z;
    int w = threadIdx.x;
    int row = b * NPOS + (h >> 4) * 14 + (w >> 4);
    int f = (c << 8) + ((h & 15) << 4) + (w & 15);
    size_t o = (((size_t)b * 3 + c) * 224 + h) * 224 + w;
    size_t s = (size_t)row * DD + f;
    out[o] = X[s] - Df[s];
}

__global__ void diffout_kernel(const float* __restrict__ Df, float* __restrict__ out)
{
    int b = blockIdx.x;
    int fbase = blockIdx.y * 8;
    for (int idx = threadIdx.x; idx < 8 * NPOS; idx += blockDim.x) {
        int f = fbase + idx / NPOS;
        int p = idx - (idx / NPOS) * NPOS;
        out[((size_t)b * DD + f) * NPOS + p] = Df[((size_t)(b * NPOS + p)) * DD + f];
    }
}

// ---------------- launch ----------------
extern "C" void kernel_launch(void* const* d_in, const int* in_sizes, int n_in,
                              void* d_out, int out_size)
{
    const float* data = (const float*)d_in[0];
    const float* c0 = (const float*)d_in[1];
    const float* c1 = (const float*)d_in[2];
    const float* c2 = (const float*)d_in[3];
    const float* e0 = (const float*)d_in[4];
    const float* e1 = (const float*)d_in[5];
    const float* e2 = (const float*)d_in[6];
    float* out = (float*)d_out;

    void *pX, *pD1, *pD2, *pAt, *pB0, *pB1, *pB2, *pN, *pTB, *pTS, *pC0, *pC1, *pC2, *pF, *pCnt;
    cudaGetSymbolAddress(&pX, g_X);
    cudaGetSymbolAddress(&pD1, g_D1);
    cudaGetSymbolAddress(&pD2, g_D2);
    cudaGetSymbolAddress(&pAt, g_At);
    cudaGetSymbolAddress(&pB0, g_B0t);
    cudaGetSymbolAddress(&pB1, g_B1t);
    cudaGetSymbolAddress(&pB2, g_B2t);
    cudaGetSymbolAddress(&pN, g_norms);
    cudaGetSymbolAddress(&pTB, g_tb);
    cudaGetSymbolAddress(&pTS, g_ts);
    cudaGetSymbolAddress(&pC0, g_cls0);
    cudaGetSymbolAddress(&pC1, g_cls1);
    cudaGetSymbolAddress(&pC2, g_cls2);
    cudaGetSymbolAddress(&pF, g_flags);
    cudaGetSymbolAddress(&pCnt, g_cnt);
    float* X = (float*)pX;
    float* D1 = (float*)pD1;
    float* D2 = (float*)pD2;
    float* At = (float*)pAt;
    float* B0t = (float*)pB0;
    float* B1t = (float*)pB1;
    float* B2t = (float*)pB2;
    float* nrm = (float*)pN;
    unsigned long long* tb = (unsigned long long*)pTB;
    float* ts = (float*)pTS;
    int* cls0 = (int*)pC0;
    int* cls1 = (int*)pC1;
    int* cls2 = (int*)pC2;
    int* flags = (int*)pF;
    int* cnt = (int*)pCnt;

    cudaFuncSetAttribute(score_mma_kernel, cudaFuncAttributeMaxDynamicSharedMemorySize, SMEM_TOTAL);

    dim3 t32(32, 8);

    patchify_kernel<<<ROWS_TOTAL, 256>>>(data, X);
    norms_kernel<<<NC0, 256>>>(c0, nrm);
    norms_kernel<<<NC1, 256>>>(c1, nrm + NC0);
    norms_kernel<<<NC2, 256>>>(c2, nrm + NC0 + NC1);
    trans_kernel<<<dim3(24, NC0 / 32), t32>>>(c0, B0t, NC0, nullptr);
    trans_kernel<<<dim3(24, NC1 / 32), t32>>>(c1, B1t, NC1, nullptr);
    trans_kernel<<<dim3(24, NC2 / 32), t32>>>(c2, B2t, NC2, nullptr);

    // stage 0
    trans_kernel<<<dim3(24, ROWS_TOTAL / 32), t32>>>(X, At, ROWS_TOTAL, cnt);
    score_mma_kernel<<<dim3(ROWS_TOTAL / TM, NC0 / TN), 256, SMEM_TOTAL>>>(At, B0t, NC0, nrm, tb, ts);
    reduce_kernel<<<ROWS_TOTAL, 32>>>(tb, ts, NC0 / TN, cls0, flags, cnt);
    fixup_kernel<<<148, 256>>>(X, c0, nrm, NC0, flags, cnt, cls0);
    gather_kernel<<<ROWS_TOTAL, 192>>>(X, c0, cls0, D1);

    // stage 1
    trans_kernel<<<dim3(24, ROWS_TOTAL / 32), t32>>>(D1, At, ROWS_TOTAL, cnt);
    score_mma_kernel<<<dim3(ROWS_TOTAL / TM, NC1 / TN), 256, SMEM_TOTAL>>>(At, B1t, NC1, nrm + NC0, tb, ts);
    reduce_kernel<<<ROWS_TOTAL, 32>>>(tb, ts, NC1 / TN, cls1, flags, cnt);
    fixup_kernel<<<148, 256>>>(D1, c1, nrm + NC0, NC1, flags, cnt, cls1);
    gather_kernel<<<ROWS_TOTAL, 192>>>(D1, c1, cls1, D2);

    // stage 2
    trans_kernel<<<dim3(24, ROWS_TOTAL / 32), t32>>>(D2, At, ROWS_TOTAL, cnt);
    score_mma_kernel<<<dim3(ROWS_TOTAL / TM, NC2 / TN), 256, SMEM_TOTAL>>>(At, B2t, NC2, nrm + NC0 + NC1, tb, ts);
    reduce_kernel<<<ROWS_TOTAL, 32>>>(tb, ts, NC2 / TN, cls2, flags, cnt);
    fixup_kernel<<<148, 256>>>(D2, c2, nrm + NC0 + NC1, NC2, flags, cnt, cls2);
    gather_kernel<<<ROWS_TOTAL, 192>>>(D2, c2, cls2, D1);

    // outputs: [embed | img_sum | diff_out]
    embed_kernel<<<dim3(NB, EMBD / 8), 256>>>(e0, e1, e2, cls0, cls1, cls2, out);
    img_kernel<<<dim3(NB, 3, 224), 224>>>(X, D1, out + OUTSLICE);
    diffout_kernel<<<dim3(NB, DD / 8), 256>>>(D1, out + 2 * OUTSLICE);
}

// round 7
// speedup vs baseline: 2.7506x; 2.7506x over previous
#include <cuda_runtime.h>
#include <cstdint>

// Problem constants
#define NB        32
#define D         768
#define EMBD      768
#define NPOS      196        // 14*14 patches per image
#define ROWS_TOTAL 6272      // NB * NPOS
#define NC0       512
#define NC1       2048
#define NC2       8192
#define OUTSLICE  4816896    // 32*768*196 == 32*3*224*224

// GEMM tiling
#define BM 128
#define BN 128
#define BK 16
#define BROW 140   // padded B smem row stride (words); 140 % 32 == 12

// ---------------- scratch (static device memory; no allocation) ----------------
__device__ float g_X [ROWS_TOTAL * D];
__device__ float g_D1[ROWS_TOTAL * D];
__device__ float g_D2[ROWS_TOTAL * D];
__device__ float g_norms[NC0 + NC1 + NC2];
__device__ unsigned long long g_best[ROWS_TOTAL];
__device__ int g_cls0[ROWS_TOTAL];
__device__ int g_cls1[ROWS_TOTAL];
__device__ int g_cls2[ROWS_TOTAL];

// ---------------- helpers ----------------
__device__ __forceinline__ unsigned long long pk2(float v) {
    unsigned long long r;
    asm("mov.b64 %0, {%1, %1};" : "=l"(r) : "f"(v));
    return r;
}
__device__ __forceinline__ void ffma2(unsigned long long& d, unsigned long long a, unsigned long long b) {
    asm("fma.rn.f32x2 %0, %1, %2, %0;" : "+l"(d) : "l"(a), "l"(b));
}
__device__ __forceinline__ void unpk(unsigned long long v, float& lo, float& hi) {
    asm("mov.b64 {%0, %1}, %2;" : "=f"(lo), "=f"(hi) : "l"(v));
}
// order-preserving float -> uint key (ascending)
__device__ __forceinline__ unsigned fkey(float f) {
    unsigned u = __float_as_uint(f);
    return (u & 0x80000000u) ? ~u : (u | 0x80000000u);
}

// ---------------- patchify: data[b,3,224,224] -> X[row, f] ----------------
__global__ void patchify_kernel(const float* __restrict__ data, float* __restrict__ X) {
    int row = blockIdx.x;
    int b  = row / NPOS;
    int p  = row - b * NPOS;
    int ph = p / 14;
    int pw = p - ph * 14;
    const float* src = data + (size_t)b * 3 * 224 * 224;
    float* dst = X + (size_t)row * D;
    for (int f = threadIdx.x; f < D; f += blockDim.x) {
        int c = f >> 8;
        int i = (f >> 4) & 15;
        int j = f & 15;
        dst[f] = src[((size_t)c * 224 + (ph * 16 + i)) * 224 + (pw * 16 + j)];
    }
}

// ---------------- ||c||^2 per center ----------------
__global__ void norms_kernel(const float* __restrict__ C, float* __restrict__ out) {
    int k = blockIdx.x;
    const float* row = C + (size_t)k * D;
    float s = 0.f;
    for (int i = threadIdx.x; i < D; i += 256) {
        float v = row[i];
        s += v * v;
    }
    #pragma unroll
    for (int o = 16; o; o >>= 1) s += __shfl_xor_sync(0xffffffffu, s, o);
    __shared__ float red[8];
    if ((threadIdx.x & 31) == 0) red[threadIdx.x >> 5] = s;
    __syncthreads();
    if (threadIdx.x == 0) {
        float t = 0.f;
        #pragma unroll
        for (int w = 0; w < 8; w++) t += red[w];
        out[k] = t;
    }
}

// ---------------- init best to +inf key ----------------
__global__ void init_best_kernel(unsigned long long* __restrict__ best) {
    int i = blockIdx.x * 256 + threadIdx.x;
    if (i < ROWS_TOTAL) best[i] = ~0ull;
}

// ---------------- fused GEMM + argmin (128x128 tile) ----------------
// scores[r, n] = norms[n] - 2 * dot(X[r], C[n]); atomicMin of packed (key, idx)
__global__ __launch_bounds__(256, 2) void score_kernel(
    const float* __restrict__ X, const float* __restrict__ C,
    const float* __restrict__ norms, unsigned long long* __restrict__ best)
{
    __shared__ __align__(16) float As[BK][BM];
    __shared__ __align__(16) float Bs[BK][BROW];
    __shared__ unsigned long long red[BM];

    const int tid = threadIdx.x;
    const int tx = tid & 15;             // 8 N-cols each: n = tx*8 .. tx*8+7
    const int ty = tid >> 4;             // 8 M-rows each: m = ty*8 .. ty*8+7
    const int rowTile = blockIdx.x * BM;
    const int colTile = blockIdx.y * BN;

    // global->smem load mapping (float4 per thread)
    const int ar0  = tid >> 2;           // 0..63
    const int ak   = (tid & 3) << 2;     // k offset {0,4,8,12}
    const int aswz = (tid & 3) << 3;     // A XOR swizzle {0,8,16,24}

    // B store word offsets (gap-padded layout: w(n) = n + 4*(n>>5))
    const int bw0 = ar0 + ((ar0 >> 5) << 2);
    const int bw1 = (ar0 + 64) + (((ar0 + 64) >> 5) << 2);
    // B read word offsets for this thread's two LDS.128
    const int rb0 = tx * 8;
    const int rb1 = tx * 8 + 4;
    const int rw0 = rb0 + ((rb0 >> 5) << 2);
    const int rw1 = rb1 + ((rb1 >> 5) << 2);

    unsigned long long acc[4][8];
    #pragma unroll
    for (int i = 0; i < 4; i++)
        #pragma unroll
        for (int j = 0; j < 8; j++) acc[i][j] = 0ull;

    const float* Xbase  = X + (size_t)(rowTile + ar0) * D + ak;
    const float* Xbase2 = Xbase + (size_t)64 * D;
    const float* Cb0    = C + (size_t)(colTile + ar0) * D + ak;
    const float* Cb1    = Cb0 + (size_t)64 * D;

    float4 pa0 = *(const float4*)(Xbase);
    float4 pa1 = *(const float4*)(Xbase2);
    float4 pb0 = *(const float4*)(Cb0);
    float4 pb1 = *(const float4*)(Cb1);

    for (int kt = 0; kt < D; kt += BK) {
        // store current tile to smem (conflict-free patterns)
        {
            int ca  = ar0 ^ aswz;
            As[ak + 0][ca] = pa0.x; As[ak + 1][ca] = pa0.y;
            As[ak + 2][ca] = pa0.z; As[ak + 3][ca] = pa0.w;
            int ca2 = (ar0 + 64) ^ aswz;
            As[ak + 0][ca2] = pa1.x; As[ak + 1][ca2] = pa1.y;
            As[ak + 2][ca2] = pa1.z; As[ak + 3][ca2] = pa1.w;
            Bs[ak + 0][bw0] = pb0.x; Bs[ak + 1][bw0] = pb0.y;
            Bs[ak + 2][bw0] = pb0.z; Bs[ak + 3][bw0] = pb0.w;
            Bs[ak + 0][bw1] = pb1.x; Bs[ak + 1][bw1] = pb1.y;
            Bs[ak + 2][bw1] = pb1.z; Bs[ak + 3][bw1] = pb1.w;
        }
        __syncthreads();

        // prefetch next tile
        if (kt + BK < D) {
            pa0 = *(const float4*)(Xbase  + kt + BK);
            pa1 = *(const float4*)(Xbase2 + kt + BK);
            pb0 = *(const float4*)(Cb0 + kt + BK);
            pb1 = *(const float4*)(Cb1 + kt + BK);
        }

        // compute: 4 M-pairs x 8 N per kk
        #pragma unroll
        for (int kk = 0; kk < BK; kk++) {
            const int offs = ((kk >> 2) & 3) << 3;
            const int sa = (ty * 8) ^ offs;
            ulonglong2 a01 = *(const ulonglong2*)&As[kk][sa];
            ulonglong2 a23 = *(const ulonglong2*)&As[kk][sa + 4];
            float4 bv0 = *(const float4*)&Bs[kk][rw0];
            float4 bv1 = *(const float4*)&Bs[kk][rw1];
            unsigned long long b[8];
            b[0] = pk2(bv0.x); b[1] = pk2(bv0.y); b[2] = pk2(bv0.z); b[3] = pk2(bv0.w);
            b[4] = pk2(bv1.x); b[5] = pk2(bv1.y); b[6] = pk2(bv1.z); b[7] = pk2(bv1.w);
            unsigned long long A0 = a01.x, A1 = a01.y, A2v = a23.x, A3 = a23.y;
            #pragma unroll
            for (int j = 0; j < 8; j++) {
                ffma2(acc[0][j], A0, b[j]);
                ffma2(acc[1][j], A1, b[j]);
                ffma2(acc[2][j], A2v, b[j]);
                ffma2(acc[3][j], A3, b[j]);
            }
        }
        __syncthreads();
    }

    // per-thread argmin over its 8 columns, then block/global reduction
    float nrm[8];
    #pragma unroll
    for (int j = 0; j < 8; j++) nrm[j] = norms[colTile + tx * 8 + j];

    if (tid < BM) red[tid] = ~0ull;
    __syncthreads();

    #pragma unroll
    for (int i = 0; i < 4; i++) {
        float lo[8], hi[8];
        #pragma unroll
        for (int j = 0; j < 8; j++) unpk(acc[i][j], lo[j], hi[j]);

        // row = ty*8 + 2i (lo lane)
        {
            float bs = nrm[0] - 2.f * lo[0];
            int bn = 0;
            #pragma unroll
            for (int j = 1; j < 8; j++) {
                float s = nrm[j] - 2.f * lo[j];
                if (s < bs) { bs = s; bn = j; }
            }
            unsigned long long key =
                ((unsigned long long)fkey(bs) << 32) | (unsigned)(colTile + tx * 8 + bn);
            atomicMin(&red[ty * 8 + 2 * i], key);
        }
        // row = ty*8 + 2i + 1 (hi lane)
        {
            float bs = nrm[0] - 2.f * hi[0];
            int bn = 0;
            #pragma unroll
            for (int j = 1; j < 8; j++) {
                float s = nrm[j] - 2.f * hi[j];
                if (s < bs) { bs = s; bn = j; }
            }
            unsigned long long key =
                ((unsigned long long)fkey(bs) << 32) | (unsigned)(colTile + tx * 8 + bn);
            atomicMin(&red[ty * 8 + 2 * i + 1], key);
        }
    }
    __syncthreads();
    if (tid < BM) atomicMin(&best[rowTile + tid], red[tid]);
}

// ---------------- gather: diff = prev - C[cls]; record cls ----------------
__global__ void gather_kernel(const float* __restrict__ prev, const float* __restrict__ C,
                              const unsigned long long* __restrict__ best,
                              float* __restrict__ outd, int* __restrict__ cls)
{
    int row = blockIdx.x;
    int k = (int)(best[row] & 0xffffffffull);
    if (threadIdx.x == 0) cls[row] = k;
    const float4* pr = (const float4*)(prev + (size_t)row * D);
    const float4* cr = (const float4*)(C + (size_t)k * D);
    float4* orow = (float4*)(outd + (size_t)row * D);
    for (int f = threadIdx.x; f < D / 4; f += blockDim.x) {
        float4 a = pr[f];
        float4 b = cr[f];
        orow[f] = make_float4(a.x - b.x, a.y - b.y, a.z - b.z, a.w - b.w);
    }
}

// ---------------- embed: out[b, e, ph, pw] = e0[cls0]+e1[cls1]+e2[cls2] ----------------
__global__ void embed_kernel(const float* __restrict__ e0, const float* __restrict__ e1,
                             const float* __restrict__ e2,
                             const int* __restrict__ cls0, const int* __restrict__ cls1,
                             const int* __restrict__ cls2, float* __restrict__ out)
{
    int b = blockIdx.x;
    int ebase = blockIdx.y * 8;
    __shared__ int s0[NPOS], s1[NPOS], s2[NPOS];
    for (int p = threadIdx.x; p < NPOS; p += blockDim.x) {
        int r = b * NPOS + p;
        s0[p] = cls0[r]; s1[p] = cls1[r]; s2[p] = cls2[r];
    }
    __syncthreads();
    for (int idx = threadIdx.x; idx < 8 * NPOS; idx += blockDim.x) {
        int e = ebase + idx / NPOS;
        int p = idx - (idx / NPOS) * NPOS;
        out[((size_t)b * EMBD + e) * NPOS + p] =
            e0[(size_t)s0[p] * EMBD + e] +
            e1[(size_t)s1[p] * EMBD + e] +
            e2[(size_t)s2[p] * EMBD + e];
    }
}

// ---------------- img_sum: out[b,c,h,w] = X - finalDiff (image layout) ----------------
__global__ void img_kernel(const float* __restrict__ X, const float* __restrict__ Df,
                           float* __restrict__ out)
{
    int b = blockIdx.x, c = blockIdx.y, h = blockIdx.z;
    int w = threadIdx.x;
    int row = b * NPOS + (h >> 4) * 14 + (w >> 4);
    int f = (c << 8) + ((h & 15) << 4) + (w & 15);
    size_t o = (((size_t)b * 3 + c) * 224 + h) * 224 + w;
    size_t s = (size_t)row * D + f;
    out[o] = X[s] - Df[s];
}

// ---------------- diff_out: out[b, f, ph, pw] = finalDiff[row, f] ----------------
__global__ void diffout_kernel(const float* __restrict__ Df, float* __restrict__ out)
{
    int b = blockIdx.x;
    int fbase = blockIdx.y * 8;
    for (int idx = threadIdx.x; idx < 8 * NPOS; idx += blockDim.x) {
        int f = fbase + idx / NPOS;
        int p = idx - (idx / NPOS) * NPOS;
        out[((size_t)b * D + f) * NPOS + p] = Df[((size_t)(b * NPOS + p)) * D + f];
    }
}

// ---------------- launch ----------------
extern "C" void kernel_launch(void* const* d_in, const int* in_sizes, int n_in,
                              void* d_out, int out_size)
{
    const float* data = (const float*)d_in[0];
    const float* c0 = (const float*)d_in[1];
    const float* c1 = (const float*)d_in[2];
    const float* c2 = (const float*)d_in[3];
    const float* e0 = (const float*)d_in[4];
    const float* e1 = (const float*)d_in[5];
    const float* e2 = (const float*)d_in[6];
    float* out = (float*)d_out;

    void *pX, *pD1, *pD2, *pN, *pB, *pC0, *pC1, *pC2;
    cudaGetSymbolAddress(&pX, g_X);
    cudaGetSymbolAddress(&pD1, g_D1);
    cudaGetSymbolAddress(&pD2, g_D2);
    cudaGetSymbolAddress(&pN, g_norms);
    cudaGetSymbolAddress(&pB, g_best);
    cudaGetSymbolAddress(&pC0, g_cls0);
    cudaGetSymbolAddress(&pC1, g_cls1);
    cudaGetSymbolAddress(&pC2, g_cls2);
    float* X  = (float*)pX;
    float* D1 = (float*)pD1;
    float* D2 = (float*)pD2;
    float* nrm = (float*)pN;
    unsigned long long* best = (unsigned long long*)pB;
    int* cls0 = (int*)pC0;
    int* cls1 = (int*)pC1;
    int* cls2 = (int*)pC2;

    patchify_kernel<<<ROWS_TOTAL, 256>>>(data, X);
    norms_kernel<<<NC0, 256>>>(c0, nrm);
    norms_kernel<<<NC1, 256>>>(c1, nrm + NC0);
    norms_kernel<<<NC2, 256>>>(c2, nrm + NC0 + NC1);

    // stage 0
    init_best_kernel<<<(ROWS_TOTAL + 255) / 256, 256>>>(best);
    score_kernel<<<dim3(ROWS_TOTAL / BM, NC0 / BN), 256>>>(X, c0, nrm, best);
    gather_kernel<<<ROWS_TOTAL, 192>>>(X, c0, best, D1, cls0);

    // stage 1
    init_best_kernel<<<(ROWS_TOTAL + 255) / 256, 256>>>(best);
    score_kernel<<<dim3(ROWS_TOTAL / BM, NC1 / BN), 256>>>(D1, c1, nrm + NC0, best);
    gather_kernel<<<ROWS_TOTAL, 192>>>(D1, c1, best, D2, cls1);

    // stage 2
    init_best_kernel<<<(ROWS_TOTAL + 255) / 256, 256>>>(best);
    score_kernel<<<dim3(ROWS_TOTAL / BM, NC2 / BN), 256>>>(D2, c2, nrm + NC0 + NC1, best);
    gather_kernel<<<ROWS_TOTAL, 192>>>(D2, c2, best, D1, cls2);

    // outputs: [embed | img_sum | diff_out]
    embed_kernel<<<dim3(NB, EMBD / 8), 256>>>(e0, e1, e2, cls0, cls1, cls2, out);
    img_kernel<<<dim3(NB, 3, 224), 224>>>(X, D1, out + OUTSLICE);
    diffout_kernel<<<dim3(NB, D / 8), 256>>>(D1, out + 2 * OUTSLICE);
}